// round 6
// baseline (speedup 1.0000x reference)
#include <cuda_runtime.h>

#define DD 160
#define HH 192
#define WW 160
#define DHW (DD*HH*WW)

// Trilinear sample of src with zeros padding.
// Row-wise vectorized gather: 4 (z,y) rows, one aligned float4 per row
// covering both x-corners 75% of the time; rare scalar fixup otherwise.
__device__ __forceinline__ float sample1(const float* __restrict__ v,
                                         float ix, float iy, float iz) {
    if (ix <= -1.0f || ix >= (float)WW ||
        iy <= -1.0f || iy >= (float)HH ||
        iz <= -1.0f || iz >= (float)DD) return 0.0f;
    float x0f = floorf(ix), y0f = floorf(iy), z0f = floorf(iz);
    int x0 = (int)x0f, y0 = (int)y0f, z0 = (int)z0f;
    float tx = ix - x0f, ty = iy - y0f, tz = iz - z0f;

    // x geometry (shared by all 4 rows)
    int x1  = x0 + 1;
    int x0c = min(max(x0, 0), WW - 1);
    int x1c = min(max(x1, 0), WW - 1);
    float wx0 = ((unsigned)x0 < (unsigned)WW) ? (1.0f - tx) : 0.0f;
    float wx1 = ((unsigned)x1 < (unsigned)WW) ? tx : 0.0f;
    int a  = x0c & ~3;
    int ax = x0c & 3;
    int bx = x1c - a;            // in {0..4}; 4 => fixup needed
    float cw0 = (ax == 0 ? wx0 : 0.0f) + (bx == 0 ? wx1 : 0.0f);
    float cw1 = (ax == 1 ? wx0 : 0.0f) + (bx == 1 ? wx1 : 0.0f);
    float cw2 = (ax == 2 ? wx0 : 0.0f) + (bx == 2 ? wx1 : 0.0f);
    float cw3 = (ax == 3 ? wx0 : 0.0f) + (bx == 3 ? wx1 : 0.0f);

    // 4 rows: (dz,dy) in {0,1}^2
    int   rowoff[4];
    float wrow[4];
    #pragma unroll
    for (int r = 0; r < 4; r++) {
        int dz = r >> 1, dy = r & 1;
        int zc = z0 + dz, yc = y0 + dy;
        int zi = min(max(zc, 0), DD - 1);
        int yi = min(max(yc, 0), HH - 1);
        bool inb = ((unsigned)zc < (unsigned)DD) & ((unsigned)yc < (unsigned)HH);
        rowoff[r] = (zi * HH + yi) * WW + a;
        float w = (dz ? tz : 1.0f - tz) * (dy ? ty : 1.0f - ty);
        wrow[r] = inb ? w : 0.0f;
    }

    // batched row loads (MLP = 4)
    float4 q0 = __ldg((const float4*)(v + rowoff[0]));
    float4 q1 = __ldg((const float4*)(v + rowoff[1]));
    float4 q2 = __ldg((const float4*)(v + rowoff[2]));
    float4 q3 = __ldg((const float4*)(v + rowoff[3]));

    float d0 = fmaf(q0.x, cw0, fmaf(q0.y, cw1, fmaf(q0.z, cw2, q0.w * cw3)));
    float d1 = fmaf(q1.x, cw0, fmaf(q1.y, cw1, fmaf(q1.z, cw2, q1.w * cw3)));
    float d2 = fmaf(q2.x, cw0, fmaf(q2.y, cw1, fmaf(q2.z, cw2, q2.w * cw3)));
    float d3 = fmaf(q3.x, cw0, fmaf(q3.y, cw1, fmaf(q3.z, cw2, q3.w * cw3)));

    float acc = fmaf(wrow[0], d0, fmaf(wrow[1], d1,
                fmaf(wrow[2], d2, wrow[3] * d3)));

    if (bx == 4) {   // x1c = a+4: one scalar per row, weight wx1
        float fs = fmaf(wrow[0], __ldg(v + rowoff[0] + 4),
                   fmaf(wrow[1], __ldg(v + rowoff[1] + 4),
                   fmaf(wrow[2], __ldg(v + rowoff[2] + 4),
                        wrow[3] * __ldg(v + rowoff[3] + 4))));
        acc = fmaf(wx1, fs, acc);
    }
    return acc;
}

__device__ __forceinline__ void sample3(const float* __restrict__ v,
                                        float ix, float iy, float iz,
                                        float& o0, float& o1, float& o2) {
    o0 = 0.0f; o1 = 0.0f; o2 = 0.0f;
    // practically always fully out of bounds -> warp-uniform early-out
    if (ix <= -1.0f || ix >= (float)WW ||
        iy <= -1.0f || iy >= (float)HH ||
        iz <= -1.0f || iz >= (float)DD) return;
    float x0f = floorf(ix), y0f = floorf(iy), z0f = floorf(iz);
    int x0 = (int)x0f, y0 = (int)y0f, z0 = (int)z0f;
    float tx = ix - x0f, ty = iy - y0f, tz = iz - z0f;
    #pragma unroll
    for (int dz = 0; dz < 2; dz++) {
        int zc = z0 + dz;
        if ((unsigned)zc >= (unsigned)DD) continue;
        float wz = dz ? tz : 1.0f - tz;
        #pragma unroll
        for (int dy = 0; dy < 2; dy++) {
            int yc = y0 + dy;
            if ((unsigned)yc >= (unsigned)HH) continue;
            float wy = dy ? ty : 1.0f - ty;
            float wzy = wz * wy;
            unsigned base = ((unsigned)zc * HH + (unsigned)yc) * WW;
            #pragma unroll
            for (int dx = 0; dx < 2; dx++) {
                int xc = x0 + dx;
                if ((unsigned)xc >= (unsigned)WW) continue;
                float w = wzy * (dx ? tx : 1.0f - tx);
                unsigned off = base + (unsigned)xc;
                o0 = fmaf(w, __ldg(v + off), o0);
                o1 = fmaf(w, __ldg(v + DHW + off), o1);
                o2 = fmaf(w, __ldg(v + 2u*DHW + off), o2);
            }
        }
    }
}

// block (32,8): warp = 32 stride-1 x at one (y,z); thread unrolls 4 consecutive y
__global__ void __launch_bounds__(256) st_kernel(
                          const float* __restrict__ src,
                          const float* __restrict__ flow1,
                          const float* __restrict__ flow2,
                          const float* __restrict__ rf_p,
                          float* __restrict__ out) {
    unsigned x  = blockIdx.x * 32u + threadIdx.x;
    unsigned z  = blockIdx.z;
    unsigned yb = blockIdx.y * 32u + threadIdx.y * 4u;

    float rf = __ldg(rf_p);
    float xf = (float)x, zf = (float)z;

    unsigned idx0 = (z * HH + yb) * WW + x;

    // front-batched flow2 loads (MLP = 12)
    float f2z[4], f2y[4], f2x[4];
    #pragma unroll
    for (int j = 0; j < 4; j++) {
        unsigned idx = idx0 + j * WW;
        f2z[j] = __ldg(flow2 + idx);
        f2y[j] = __ldg(flow2 + DHW + idx);
        f2x[j] = __ldg(flow2 + 2u*DHW + idx);
    }

    #pragma unroll
    for (int j = 0; j < 4; j++) {
        unsigned idx = idx0 + j * WW;
        float yf = (float)(yb + j);

        // grid2 = grid + flow2 * rf  (grid analytic)
        float g2z = zf + f2z[j] * rf;
        float g2y = yf + f2y[j] * rf;
        float g2x = xf + f2x[j] * rf;

        // grid_sample(flow1, grid2) coord unnorm (align_corners=False)
        float ix = ((g2x + 1.0f) * (float)WW - 1.0f) * 0.5f;
        float iy = ((g2y + 1.0f) * (float)HH - 1.0f) * 0.5f;
        float iz = ((g2z + 1.0f) * (float)DD - 1.0f) * 0.5f;

        float w0, w1, w2;
        sample3(flow1, ix, iy, iz, w0, w1, w2);

        // out_flow = flow1_warped + flow2
        float oz = w0 + f2z[j];
        float oy = w1 + f2y[j];
        float ox = w2 + f2x[j];

        // new_locs_total = grid + out_flow*rf -> normalize -> unnorm
        float vz = zf + oz * rf;
        float vy = yf + oy * rf;
        float vx = xf + ox * rf;

        float nz = 2.0f * (vz / (float)(DD - 1) - 0.5f);
        float ny = 2.0f * (vy / (float)(HH - 1) - 0.5f);
        float nx = 2.0f * (vx / (float)(WW - 1) - 0.5f);

        float sx = ((nx + 1.0f) * (float)WW - 1.0f) * 0.5f;
        float sy = ((ny + 1.0f) * (float)HH - 1.0f) * 0.5f;
        float sz = ((nz + 1.0f) * (float)DD - 1.0f) * 0.5f;

        float img = sample1(src, sx, sy, sz);

        out[idx]            = img;
        out[DHW + idx]      = oz;
        out[2u*DHW + idx]   = oy;
        out[3u*DHW + idx]   = ox;
    }
}

extern "C" void kernel_launch(void* const* d_in, const int* in_sizes, int n_in,
                              void* d_out, int out_size) {
    const float* src   = (const float*)d_in[0];
    const float* flow1 = (const float*)d_in[1];
    const float* flow2 = (const float*)d_in[2];
    // d_in[3] meshgrid — analytic, not loaded
    const float* rf    = (const float*)d_in[4];
    float* out = (float*)d_out;

    dim3 block(32, 8);
    dim3 grid(WW / 32, HH / 32, DD);
    st_kernel<<<grid, block>>>(src, flow1, flow2, rf, out);
}